// round 14
// baseline (speedup 1.0000x reference)
#include <cuda_runtime.h>

// Problem geometry (fixed by reference)
#define NCH    2560      // readout channels
#define NT     256       // ticks
#define NT16   64        // 16B chunks (ulonglong2) per row
#define NCELLS 40000     // cells per face
#define NSUB   4         // sub-buckets per channel (atomic-contention spread)
#define SUBCAP 96        // capacity per sub-bucket (expected ~24; 4x margin)
#define CAPTOT (NSUB * SUBCAP)   // 384 max entries per channel

// ---- static device scratch (no allocation allowed) ----
__device__ __align__(16) int g_counts[NCH * NSUB];  // zero-init; main re-zeroes
__device__ ushort2 g_entries[NCH * CAPTOT];         // per-channel partner pairs
__device__ float   g_wf[8];                         // folded weights + bias

typedef unsigned long long u64;

// Packed f32x2 FMA (sm_100+): d = a*b+c on both 32-bit halves. SASS: FFMA2.
__device__ __forceinline__ u64 fma2(u64 a, u64 b, u64 c) {
    u64 d;
    asm("fma.rn.f32x2 %0, %1, %2, %3;" : "=l"(d) : "l"(a), "l"(b), "l"(c));
    return d;
}
__device__ __forceinline__ float lo32(u64 v) { return __uint_as_float((unsigned)v); }
__device__ __forceinline__ float hi32(u64 v) { return __uint_as_float((unsigned)(v >> 32)); }
__device__ __forceinline__ u64 pack2(float a, float b) {
    return (u64)__float_as_uint(a) | ((u64)__float_as_uint(b) << 32);
}

// Read logical element i from an index table that may be int32 or int64
// (little-endian: lo word first; all values nonnegative < 2^31).
__device__ __forceinline__ int idx_ld(const int* p, int i, bool is64) {
    return is64 ? p[2 * i] : p[i];
}

#define PREP_BLOCKS  640                    // 640*256 threads, one float4 each = NCH*NT/4
#define BUILD_BLOCKS 313                    // ceil(80000/256)

// Fused pre-kernel: relu -> out plane0 (blocks [0,PREP)), bucket build
// (blocks [PREP, PREP+BUILD)), weight fold (last block). g_counts is zero
// (module init on run 1; main_kernel resets it every run).
__global__ void pre_kernel(const float* __restrict__ x, float* __restrict__ out,
                           const float* __restrict__ W1, const float* __restrict__ b1,
                           const float* __restrict__ W2, const float* __restrict__ b2,
                           const int* __restrict__ gi0, const int* __restrict__ gi1,
                           const int* __restrict__ wc00, const int* __restrict__ wc01,
                           const int* __restrict__ wc02, const int* __restrict__ wc10,
                           const int* __restrict__ wc11, const int* __restrict__ wc12) {
    int b = blockIdx.x, tid = threadIdx.x;
    if (b < PREP_BLOCKS) {
        int i = b * 256 + tid;                      // float4 index, < 163840
        float4 v = ((const float4*)x)[i];
        v.x = fmaxf(v.x, 0.f); v.y = fmaxf(v.y, 0.f);
        v.z = fmaxf(v.z, 0.f); v.w = fmaxf(v.w, 0.f);
        ((float4*)out)[i] = v;                      // plane 0 = relu(x); also main's gather src
        return;
    }
    if (b < PREP_BLOCKS + BUILD_BLOCKS) {
        int gid = (b - PREP_BLOCKS) * 256 + tid;
        if (gid >= 2 * NCELLS) return;
        // dtype sniff: int64 => these words are hi-halves (all 0). For int32
        // they are three distinct permutation channels (at most one can be 0).
        bool is64 = (wc00[1] == 0 && wc00[3] == 0 && wc00[5] == 0);
        int f = gid / NCELLS;
        int n = gid - f * NCELLS;
        const int* gi = f ? gi1 : gi0;
        const int* wa = f ? wc10 : wc00;
        const int* wb = f ? wc11 : wc01;
        const int* wd = f ? wc12 : wc02;

        int w0 = idx_ld(gi, n * 3 + 0, is64);
        int w1 = idx_ld(gi, n * 3 + 1, is64);
        int w2 = idx_ld(gi, n * 3 + 2, is64);
        int c0 = idx_ld(wa, w0 * 2 + 1, is64);      // plane 0, in [0,800)
        int c1 = idx_ld(wb, w1 * 2 + 1, is64);      // plane 1, in [800,1600)
        int c2 = idx_ld(wd, w2 * 2 + 1, is64);      // plane 2, in [1600,2560)

        // Bucket c stores the OTHER two channels (slot implied by c's range).
        // Sub-bucket (gid&3) spreads atomic contention 4x per channel.
        int sub = gid & (NSUB - 1);
        int s0 = atomicAdd(&g_counts[c0 * NSUB + sub], 1);
        if (s0 < SUBCAP) g_entries[c0 * CAPTOT + sub * SUBCAP + s0] =
            make_ushort2((unsigned short)c1, (unsigned short)c2);
        int s1 = atomicAdd(&g_counts[c1 * NSUB + sub], 1);
        if (s1 < SUBCAP) g_entries[c1 * CAPTOT + sub * SUBCAP + s1] =
            make_ushort2((unsigned short)c0, (unsigned short)c2);
        int s2 = atomicAdd(&g_counts[c2 * NSUB + sub], 1);
        if (s2 < SUBCAP) g_entries[c2 * CAPTOT + sub * SUBCAP + s2] =
            make_ushort2((unsigned short)c0, (unsigned short)c1);
        return;
    }
    // fold block: W1(3x8)@W2(8x2), beff = b1@W2 + b2
    if (tid == 0) {
        float s0 = b2[0], s1 = b2[1];
        float a[6] = {0.f, 0.f, 0.f, 0.f, 0.f, 0.f};
        #pragma unroll
        for (int h = 0; h < 8; ++h) {
            float v0 = W2[h * 2 + 0], v1 = W2[h * 2 + 1];
            s0 = fmaf(b1[h], v0, s0);
            s1 = fmaf(b1[h], v1, s1);
            #pragma unroll
            for (int r = 0; r < 3; ++r) {
                a[r]     = fmaf(W1[r * 8 + h], v0, a[r]);
                a[r + 3] = fmaf(W1[r * 8 + h], v1, a[r + 3]);
            }
        }
        #pragma unroll
        for (int r = 0; r < 6; ++r) g_wf[r] = a[r];
        g_wf[6] = s0; g_wf[7] = s1;
    }
}

// Main: one block per output channel; 64 threads, 4 ticks each (16B, LDG.128).
// Hot loop is the proven R8 form (compiler-scheduled, ushort4-paired, unroll 2).
// Prologue: single int4 load of the 4 sub-counts, then one predicated copy
// round with 4 INDEPENDENT segment loads per thread (one L2 round-trip).
__global__ __launch_bounds__(64) void main_kernel(float* __restrict__ out) {
    int c   = blockIdx.x;
    int tid = threadIdx.x;   // 0..63

    int slot = (c >= 800) + (c >= 1600);            // plane of channel c
    float ws0 = g_wf[slot],              ws1 = g_wf[3 + slot];
    float wa0 = g_wf[slot == 0 ? 1 : 0], wa1 = g_wf[slot == 0 ? 4 : 3];
    float wb0 = g_wf[slot == 2 ? 1 : 2], wb1 = g_wf[slot == 2 ? 4 : 5];
    float be0 = g_wf[6], be1 = g_wf[7];

    const ulonglong2* xr8 = (const ulonglong2*)out;   // plane 0 rows, 16B chunks
    ulonglong2 as = xr8[c * NT16 + tid];
    float sx = lo32(as.x), sy = hi32(as.x), sz = lo32(as.y), sw = hi32(as.y);
    // per-thread bases: self-plane contribution + bias (constant over entries)
    u64 base0lo = pack2(fmaf(sx, ws0, be0), fmaf(sy, ws0, be0));
    u64 base0hi = pack2(fmaf(sz, ws0, be0), fmaf(sw, ws0, be0));
    u64 base1lo = pack2(fmaf(sx, ws1, be1), fmaf(sy, ws1, be1));
    u64 base1hi = pack2(fmaf(sz, ws1, be1), fmaf(sw, ws1, be1));
    u64 wa0p = pack2(wa0, wa0), wb0p = pack2(wb0, wb0);
    u64 wa1p = pack2(wa1, wa1), wb1p = pack2(wb1, wb1);

    __shared__ ushort4 sE4[CAPTOT / 2];
    ushort2* sE = (ushort2*)sE4;

    // Single 16B load of all 4 sub-counts; compact offsets via 3 adds.
    int4 cv = ((const int4*)g_counts)[c];
    int cs0 = min(cv.x, SUBCAP), cs1 = min(cv.y, SUBCAP);
    int cs2 = min(cv.z, SUBCAP), cs3 = min(cv.w, SUBCAP);
    int o1 = cs0, o2 = cs0 + cs1, o3 = o2 + cs2, cnt = o3 + cs3;
    int mx = max(max(cs0, cs1), max(cs2, cs3));
    const ushort2* ge = &g_entries[c * CAPTOT];
    for (int i = tid; i < mx; i += 64) {            // typically 1 iteration
        if (i < cs0) sE[i]      = ge[i];
        if (i < cs1) sE[o1 + i] = ge[SUBCAP + i];
        if (i < cs2) sE[o2 + i] = ge[2 * SUBCAP + i];
        if (i < cs3) sE[o3 + i] = ge[3 * SUBCAP + i];
    }
    __syncthreads();
    if (tid == 0) ((int4*)g_counts)[c] = make_int4(0, 0, 0, 0);  // reset

    float m0x = 0.f, m0y = 0.f, m0z = 0.f, m0w = 0.f;
    float m1x = 0.f, m1y = 0.f, m1z = 0.f, m1w = 0.f;

    #define PROC(ea, eb)                                                       \
    {                                                                          \
        ulonglong2 A = xr8[(int)(ea) * NT16 + tid];                            \
        ulonglong2 B = xr8[(int)(eb) * NT16 + tid];                            \
        u64 t;                                                                 \
        t = fma2(A.x, wa0p, base0lo); t = fma2(B.x, wb0p, t);                  \
        m0x = fmaxf(m0x, lo32(t));    m0y = fmaxf(m0y, hi32(t));               \
        t = fma2(A.y, wa0p, base0hi); t = fma2(B.y, wb0p, t);                  \
        m0z = fmaxf(m0z, lo32(t));    m0w = fmaxf(m0w, hi32(t));               \
        t = fma2(A.x, wa1p, base1lo); t = fma2(B.x, wb1p, t);                  \
        m1x = fmaxf(m1x, lo32(t));    m1y = fmaxf(m1y, hi32(t));               \
        t = fma2(A.y, wa1p, base1hi); t = fma2(B.y, wb1p, t);                  \
        m1z = fmaxf(m1z, lo32(t));    m1w = fmaxf(m1w, hi32(t));               \
    }

    int npair = cnt >> 1;
    #pragma unroll 2
    for (int i = 0; i < npair; ++i) {
        ushort4 e2 = sE4[i];
        PROC(e2.x, e2.y);
        PROC(e2.z, e2.w);
    }
    if (cnt & 1) {
        ushort2 e = sE[cnt - 1];
        PROC(e.x, e.y);
    }
    #undef PROC

    // out layout (1, 3, NCH, NT): plane 0 written by pre_kernel.
    float4* o4 = (float4*)out;
    int nt4 = NT / 4;
    o4[NCH * nt4 + c * nt4 + tid]     = make_float4(m0x, m0y, m0z, m0w);
    o4[2 * NCH * nt4 + c * nt4 + tid] = make_float4(m1x, m1y, m1z, m1w);
}

extern "C" void kernel_launch(void* const* d_in, const int* in_sizes, int n_in,
                              void* d_out, int out_size) {
    const float* x  = (const float*)d_in[0];
    const float* W1 = (const float*)d_in[1];
    const float* b1 = (const float*)d_in[2];
    const float* W2 = (const float*)d_in[3];
    const float* b2 = (const float*)d_in[4];
    const int* gi0  = (const int*)d_in[5];
    const int* gi1  = (const int*)d_in[6];
    const int* wc00 = (const int*)d_in[7];
    const int* wc01 = (const int*)d_in[8];
    const int* wc02 = (const int*)d_in[9];
    const int* wc10 = (const int*)d_in[10];
    const int* wc11 = (const int*)d_in[11];
    const int* wc12 = (const int*)d_in[12];

    pre_kernel<<<PREP_BLOCKS + BUILD_BLOCKS + 1, 256>>>(
        x, (float*)d_out, W1, b1, W2, b2,
        gi0, gi1, wc00, wc01, wc02, wc10, wc11, wc12);
    main_kernel<<<NCH, 64>>>((float*)d_out);
}

// round 15
// speedup vs baseline: 1.0021x; 1.0021x over previous
#include <cuda_runtime.h>

// Problem geometry (fixed by reference)
#define NCH    2560      // readout channels
#define NT     256       // ticks
#define NT16   64        // 16B chunks (ulonglong2) per row
#define NCELLS 40000     // cells per face
#define NSUB   4         // sub-buckets per channel (atomic-contention spread)
#define SUBCAP 96        // capacity per sub-bucket (expected ~24; 4x margin)
#define CAPTOT (NSUB * SUBCAP)   // 384 max entries per channel

// ---- static device scratch (no allocation allowed) ----
__device__ __align__(16) int g_counts[NCH * NSUB];  // zero-init; main re-zeroes
__device__ ushort2 g_entries[NCH * CAPTOT];         // per-channel partner pairs
__device__ float   g_wf[8];                         // folded weights + bias

typedef unsigned long long u64;

// Packed f32x2 FMA (sm_100+): d = a*b+c on both 32-bit halves. SASS: FFMA2.
__device__ __forceinline__ u64 fma2(u64 a, u64 b, u64 c) {
    u64 d;
    asm("fma.rn.f32x2 %0, %1, %2, %3;" : "=l"(d) : "l"(a), "l"(b), "l"(c));
    return d;
}
__device__ __forceinline__ float lo32(u64 v) { return __uint_as_float((unsigned)v); }
__device__ __forceinline__ float hi32(u64 v) { return __uint_as_float((unsigned)(v >> 32)); }
__device__ __forceinline__ u64 pack2(float a, float b) {
    return (u64)__float_as_uint(a) | ((u64)__float_as_uint(b) << 32);
}
__device__ __forceinline__ unsigned us2_u32(ushort2 e) {
    return (unsigned)e.x | ((unsigned)e.y << 16);
}

// Read logical element i from an index table that may be int32 or int64
// (little-endian: lo word first; all values nonnegative < 2^31).
__device__ __forceinline__ int idx_ld(const int* p, int i, bool is64) {
    return is64 ? p[2 * i] : p[i];
}

#define PREP_BLOCKS  640                    // 640*256 threads, one float4 each = NCH*NT/4
#define BUILD_BLOCKS 313                    // ceil(80000/256)

// Fused pre-kernel: relu -> out plane0 (blocks [0,PREP)), bucket build
// (blocks [PREP, PREP+BUILD)), weight fold (last block). g_counts is zero
// (module init on run 1; main_kernel resets it every run).
__global__ void pre_kernel(const float* __restrict__ x, float* __restrict__ out,
                           const float* __restrict__ W1, const float* __restrict__ b1,
                           const float* __restrict__ W2, const float* __restrict__ b2,
                           const int* __restrict__ gi0, const int* __restrict__ gi1,
                           const int* __restrict__ wc00, const int* __restrict__ wc01,
                           const int* __restrict__ wc02, const int* __restrict__ wc10,
                           const int* __restrict__ wc11, const int* __restrict__ wc12) {
    int b = blockIdx.x, tid = threadIdx.x;
    if (b < PREP_BLOCKS) {
        int i = b * 256 + tid;                      // float4 index, < 163840
        float4 v = ((const float4*)x)[i];
        v.x = fmaxf(v.x, 0.f); v.y = fmaxf(v.y, 0.f);
        v.z = fmaxf(v.z, 0.f); v.w = fmaxf(v.w, 0.f);
        ((float4*)out)[i] = v;                      // plane 0 = relu(x); also main's gather src
        return;
    }
    if (b < PREP_BLOCKS + BUILD_BLOCKS) {
        int gid = (b - PREP_BLOCKS) * 256 + tid;
        if (gid >= 2 * NCELLS) return;
        // dtype sniff: int64 => these words are hi-halves (all 0). For int32
        // they are three distinct permutation channels (at most one can be 0).
        bool is64 = (wc00[1] == 0 && wc00[3] == 0 && wc00[5] == 0);
        int f = gid / NCELLS;
        int n = gid - f * NCELLS;
        const int* gi = f ? gi1 : gi0;
        const int* wa = f ? wc10 : wc00;
        const int* wb = f ? wc11 : wc01;
        const int* wd = f ? wc12 : wc02;

        int w0 = idx_ld(gi, n * 3 + 0, is64);
        int w1 = idx_ld(gi, n * 3 + 1, is64);
        int w2 = idx_ld(gi, n * 3 + 2, is64);
        int c0 = idx_ld(wa, w0 * 2 + 1, is64);      // plane 0, in [0,800)
        int c1 = idx_ld(wb, w1 * 2 + 1, is64);      // plane 1, in [800,1600)
        int c2 = idx_ld(wd, w2 * 2 + 1, is64);      // plane 2, in [1600,2560)

        // Bucket c stores the OTHER two channels (slot implied by c's range).
        // Sub-bucket (gid&3) spreads atomic contention 4x per channel; main
        // re-interleaves so processing order ~ gid order (cache correlation).
        int sub = gid & (NSUB - 1);
        int s0 = atomicAdd(&g_counts[c0 * NSUB + sub], 1);
        if (s0 < SUBCAP) g_entries[c0 * CAPTOT + sub * SUBCAP + s0] =
            make_ushort2((unsigned short)c1, (unsigned short)c2);
        int s1 = atomicAdd(&g_counts[c1 * NSUB + sub], 1);
        if (s1 < SUBCAP) g_entries[c1 * CAPTOT + sub * SUBCAP + s1] =
            make_ushort2((unsigned short)c0, (unsigned short)c2);
        int s2 = atomicAdd(&g_counts[c2 * NSUB + sub], 1);
        if (s2 < SUBCAP) g_entries[c2 * CAPTOT + sub * SUBCAP + s2] =
            make_ushort2((unsigned short)c0, (unsigned short)c1);
        return;
    }
    // fold block: W1(3x8)@W2(8x2), beff = b1@W2 + b2
    if (tid == 0) {
        float s0 = b2[0], s1 = b2[1];
        float a[6] = {0.f, 0.f, 0.f, 0.f, 0.f, 0.f};
        #pragma unroll
        for (int h = 0; h < 8; ++h) {
            float v0 = W2[h * 2 + 0], v1 = W2[h * 2 + 1];
            s0 = fmaf(b1[h], v0, s0);
            s1 = fmaf(b1[h], v1, s1);
            #pragma unroll
            for (int r = 0; r < 3; ++r) {
                a[r]     = fmaf(W1[r * 8 + h], v0, a[r]);
                a[r + 3] = fmaf(W1[r * 8 + h], v1, a[r + 3]);
            }
        }
        #pragma unroll
        for (int r = 0; r < 6; ++r) g_wf[r] = a[r];
        g_wf[6] = s0; g_wf[7] = s1;
    }
}

// Main: one block per output channel; 64 threads, 4 ticks each (16B, LDG.128).
// Hot loop is the proven R8 form (compiler-scheduled, ushort4-paired, unroll 2).
// Prologue INTERLEAVES the 4 sub-buckets (sE[4i+s]) so the processing order
// reconstructs ~global gid order -> cross-block cache temporal correlation.
__global__ __launch_bounds__(64) void main_kernel(float* __restrict__ out) {
    int c   = blockIdx.x;
    int tid = threadIdx.x;   // 0..63

    int slot = (c >= 800) + (c >= 1600);            // plane of channel c
    float ws0 = g_wf[slot],              ws1 = g_wf[3 + slot];
    float wa0 = g_wf[slot == 0 ? 1 : 0], wa1 = g_wf[slot == 0 ? 4 : 3];
    float wb0 = g_wf[slot == 2 ? 1 : 2], wb1 = g_wf[slot == 2 ? 4 : 5];
    float be0 = g_wf[6], be1 = g_wf[7];

    const ulonglong2* xr8 = (const ulonglong2*)out;   // plane 0 rows, 16B chunks
    ulonglong2 as = xr8[c * NT16 + tid];
    float sx = lo32(as.x), sy = hi32(as.x), sz = lo32(as.y), sw = hi32(as.y);
    // per-thread bases: self-plane contribution + bias (constant over entries)
    u64 base0lo = pack2(fmaf(sx, ws0, be0), fmaf(sy, ws0, be0));
    u64 base0hi = pack2(fmaf(sz, ws0, be0), fmaf(sw, ws0, be0));
    u64 base1lo = pack2(fmaf(sx, ws1, be1), fmaf(sy, ws1, be1));
    u64 base1hi = pack2(fmaf(sz, ws1, be1), fmaf(sw, ws1, be1));
    u64 wa0p = pack2(wa0, wa0), wb0p = pack2(wb0, wb0);
    u64 wa1p = pack2(wa1, wa1), wb1p = pack2(wb1, wb1);

    __shared__ ushort4 sE4[CAPTOT / 2];
    ushort2* sE = (ushort2*)sE4;

    // Single 16B load of all 4 sub-counts.
    int4 cv = ((const int4*)g_counts)[c];
    int cs0 = min(cv.x, SUBCAP), cs1 = min(cv.y, SUBCAP);
    int cs2 = min(cv.z, SUBCAP), cs3 = min(cv.w, SUBCAP);
    int mn  = min(min(cs0, cs1), min(cs2, cs3));
    int cnt = cs0 + cs1 + cs2 + cs3;
    const ushort2* ge = &g_entries[c * CAPTOT];
    // Dense interleave: sE[4i+s] = sub s entry i  (one STS.128 per thread).
    for (int i = tid; i < mn; i += 64) {
        ushort2 e0 = ge[i];
        ushort2 e1 = ge[SUBCAP + i];
        ushort2 e2 = ge[2 * SUBCAP + i];
        ushort2 e3 = ge[3 * SUBCAP + i];
        ((uint4*)sE)[i] = make_uint4(us2_u32(e0), us2_u32(e1),
                                     us2_u32(e2), us2_u32(e3));
    }
    // Ragged tails (few entries each), appended after the dense region.
    int t0 = 4 * mn;
    int t1 = t0 + (cs0 - mn);
    int t2 = t1 + (cs1 - mn);
    int t3 = t2 + (cs2 - mn);
    for (int i = mn + tid; i < cs0; i += 64) sE[t0 + i - mn] = ge[i];
    for (int i = mn + tid; i < cs1; i += 64) sE[t1 + i - mn] = ge[SUBCAP + i];
    for (int i = mn + tid; i < cs2; i += 64) sE[t2 + i - mn] = ge[2 * SUBCAP + i];
    for (int i = mn + tid; i < cs3; i += 64) sE[t3 + i - mn] = ge[3 * SUBCAP + i];
    __syncthreads();
    if (tid == 0) ((int4*)g_counts)[c] = make_int4(0, 0, 0, 0);  // reset

    float m0x = 0.f, m0y = 0.f, m0z = 0.f, m0w = 0.f;
    float m1x = 0.f, m1y = 0.f, m1z = 0.f, m1w = 0.f;

    #define PROC(ea, eb)                                                       \
    {                                                                          \
        ulonglong2 A = xr8[(int)(ea) * NT16 + tid];                            \
        ulonglong2 B = xr8[(int)(eb) * NT16 + tid];                            \
        u64 t;                                                                 \
        t = fma2(A.x, wa0p, base0lo); t = fma2(B.x, wb0p, t);                  \
        m0x = fmaxf(m0x, lo32(t));    m0y = fmaxf(m0y, hi32(t));               \
        t = fma2(A.y, wa0p, base0hi); t = fma2(B.y, wb0p, t);                  \
        m0z = fmaxf(m0z, lo32(t));    m0w = fmaxf(m0w, hi32(t));               \
        t = fma2(A.x, wa1p, base1lo); t = fma2(B.x, wb1p, t);                  \
        m1x = fmaxf(m1x, lo32(t));    m1y = fmaxf(m1y, hi32(t));               \
        t = fma2(A.y, wa1p, base1hi); t = fma2(B.y, wb1p, t);                  \
        m1z = fmaxf(m1z, lo32(t));    m1w = fmaxf(m1w, hi32(t));               \
    }

    int npair = cnt >> 1;
    #pragma unroll 2
    for (int i = 0; i < npair; ++i) {
        ushort4 e2 = sE4[i];
        PROC(e2.x, e2.y);
        PROC(e2.z, e2.w);
    }
    if (cnt & 1) {
        ushort2 e = sE[cnt - 1];
        PROC(e.x, e.y);
    }
    #undef PROC

    // out layout (1, 3, NCH, NT): plane 0 written by pre_kernel.
    float4* o4 = (float4*)out;
    int nt4 = NT / 4;
    o4[NCH * nt4 + c * nt4 + tid]     = make_float4(m0x, m0y, m0z, m0w);
    o4[2 * NCH * nt4 + c * nt4 + tid] = make_float4(m1x, m1y, m1z, m1w);
}

extern "C" void kernel_launch(void* const* d_in, const int* in_sizes, int n_in,
                              void* d_out, int out_size) {
    const float* x  = (const float*)d_in[0];
    const float* W1 = (const float*)d_in[1];
    const float* b1 = (const float*)d_in[2];
    const float* W2 = (const float*)d_in[3];
    const float* b2 = (const float*)d_in[4];
    const int* gi0  = (const int*)d_in[5];
    const int* gi1  = (const int*)d_in[6];
    const int* wc00 = (const int*)d_in[7];
    const int* wc01 = (const int*)d_in[8];
    const int* wc02 = (const int*)d_in[9];
    const int* wc10 = (const int*)d_in[10];
    const int* wc11 = (const int*)d_in[11];
    const int* wc12 = (const int*)d_in[12];

    pre_kernel<<<PREP_BLOCKS + BUILD_BLOCKS + 1, 256>>>(
        x, (float*)d_out, W1, b1, W2, b2,
        gi0, gi1, wc00, wc01, wc02, wc10, wc11, wc12);
    main_kernel<<<NCH, 64>>>((float*)d_out);
}